// round 6
// baseline (speedup 1.0000x reference)
#include <cuda_runtime.h>
#include <math.h>

// Problem constants (from reference: B=2,S=2048,D=2048,E=8,H=704,K=2)
#define TT 4096   // tokens = B*S
#define DD 2048   // model dim
#define EE 8      // experts
#define HH 704    // hidden dim
#define KK 2      // top-k

// ---------------- scratch (no allocations allowed) ----------------
__device__ int   g_cnt[EE];
__device__ float g_imp[EE];
__device__ float g_load[EE];
__device__ int   g_list[EE * TT];        // token id per expert slot
__device__ float g_sscore[EE * TT];      // gate score per expert slot
__device__ float g_h[EE * TT * HH];      // SwiGLU hidden per slot

// ---------------- init ----------------
__global__ void k_init() {
    int i = threadIdx.x;
    if (i < EE) { g_cnt[i] = 0; g_imp[i] = 0.f; g_load[i] = 0.f; }
}

// ---------------- zero output (d_out is poisoned; atomics need 0 base) ----------------
__global__ void k_zero(float* __restrict__ y) {
    int i = blockIdx.x * blockDim.x + threadIdx.x;
    if (i < TT * (DD / 4)) {
        ((float4*)y)[i] = make_float4(0.f, 0.f, 0.f, 0.f);
    }
}

// ---------------- gating: logits = tanh(x@Wg1)@Wg2, top-2, softmax ----------------
__global__ void k_gate(const float* __restrict__ x,
                       const float* __restrict__ Wg1,
                       const float* __restrict__ Wg2) {
    int t = blockIdx.x;
    int tid = threadIdx.x;
    __shared__ float red[128][9];
    __shared__ float t1[8];

    float p[8] = {0.f,0.f,0.f,0.f,0.f,0.f,0.f,0.f};
    const float* xr = x + (size_t)t * DD;
    for (int d = tid; d < DD; d += 128) {
        float xv = xr[d];
        const float4* w = (const float4*)(Wg1 + (size_t)d * 8);
        float4 w0 = w[0], w1 = w[1];
        p[0] += xv * w0.x; p[1] += xv * w0.y; p[2] += xv * w0.z; p[3] += xv * w0.w;
        p[4] += xv * w1.x; p[5] += xv * w1.y; p[6] += xv * w1.z; p[7] += xv * w1.w;
    }
#pragma unroll
    for (int e = 0; e < 8; e++) red[tid][e] = p[e];
    __syncthreads();
    // tree-reduce 128 partials down to 8
    for (int stride = 64; stride >= 8; stride >>= 1) {
        if (tid < stride) {
#pragma unroll
            for (int e = 0; e < 8; e++) red[tid][e] += red[tid + stride][e];
        }
        __syncthreads();
    }
    if (tid < 8) {
        t1[tid] = tanhf(red[0][tid] + red[1][tid] + red[2][tid] + red[3][tid] +
                        red[4][tid] + red[5][tid] + red[6][tid] + red[7][tid]);
    }
    __syncthreads();
    if (tid == 0) {
        float lg[8];
#pragma unroll
        for (int j = 0; j < 8; j++) {
            float s = 0.f;
#pragma unroll
            for (int e = 0; e < 8; e++) s += t1[e] * Wg2[e * 8 + j];
            lg[j] = s;
        }
        // top-2 (ties -> lower index, matching jax top_k)
        int i0 = 0; float v0 = lg[0];
#pragma unroll
        for (int j = 1; j < 8; j++) if (lg[j] > v0) { v0 = lg[j]; i0 = j; }
        int i1 = -1; float v1 = -1e30f;
#pragma unroll
        for (int j = 0; j < 8; j++) if (j != i0 && lg[j] > v1) { v1 = lg[j]; i1 = j; }
        // softmax over the two selected (v0 >= v1)
        float e1 = expf(v1 - v0);
        float inv = 1.f / (1.f + e1);
        float s0 = inv, s1 = e1 * inv;

        int p0 = atomicAdd(&g_cnt[i0], 1);
        g_list[i0 * TT + p0] = t;
        g_sscore[i0 * TT + p0] = s0;
        atomicAdd(&g_imp[i0], s0);
        if (s0 > 0.f) atomicAdd(&g_load[i0], 1.f);

        int p1 = atomicAdd(&g_cnt[i1], 1);
        g_list[i1 * TT + p1] = t;
        g_sscore[i1 * TT + p1] = s1;
        atomicAdd(&g_imp[i1], s1);
        if (s1 > 0.f) atomicAdd(&g_load[i1], 1.f);
    }
}

__device__ __forceinline__ float silu_f(float v) {
    return v / (1.f + expf(-v));
}

// ---------------- fused gate+up GEMM + SwiGLU (double-buffered via registers) ----------------
// grid: (HH/64, TT/64, EE), block 128. C[m,n] over tokens of expert e.
__global__ void __launch_bounds__(128) k_up(const float* __restrict__ x,
                                            const float* __restrict__ Wgt,
                                            const float* __restrict__ Wup) {
    int e = blockIdx.z;
    int M = g_cnt[e];
    int m0 = blockIdx.y * 64;
    if (m0 >= M) return;
    int n0 = blockIdx.x * 64;

    __shared__ float As[64][17];
    __shared__ float Bg[16][64];
    __shared__ float Bu[16][64];
    __shared__ int   tok[64];

    int tid = threadIdx.x;
    if (tid < 64) {
        int m = m0 + tid;
        tok[tid] = (m < M) ? g_list[e * TT + m] : -1;
    }
    __syncthreads();

    int tr = tid >> 4;   // 0..7 (row group)
    int tc = tid & 15;   // 0..15 (col group)
    float accG[8][4]; float accU[8][4];
#pragma unroll
    for (int i = 0; i < 8; i++)
#pragma unroll
        for (int j = 0; j < 4; j++) { accG[i][j] = 0.f; accU[i][j] = 0.f; }

    const float* wg = Wgt + (size_t)e * DD * HH;
    const float* wu = Wup + (size_t)e * DD * HH;

    // per-thread load coordinates (constant across slabs)
    int aM[2], aK[2], bK[2], bN[2];
#pragma unroll
    for (int q = 0; q < 2; q++) {
        int idx = tid * 2 + q;          // 0..255
        aM[q] = idx >> 2;
        aK[q] = (idx & 3) << 2;
        bK[q] = idx >> 4;
        bN[q] = (idx & 15) << 2;
    }

    float4 pA[2], pBg[2], pBu[2];
    // prefetch slab 0
#pragma unroll
    for (int q = 0; q < 2; q++) {
        int tkn = tok[aM[q]];
        pA[q] = (tkn >= 0) ? *(const float4*)(x + (size_t)tkn * DD + aK[q])
                           : make_float4(0.f, 0.f, 0.f, 0.f);
        pBg[q] = *(const float4*)(wg + (size_t)bK[q] * HH + n0 + bN[q]);
        pBu[q] = *(const float4*)(wu + (size_t)bK[q] * HH + n0 + bN[q]);
    }

    for (int k0 = 0; k0 < DD; k0 += 16) {
        // commit prefetched slab to smem
#pragma unroll
        for (int q = 0; q < 2; q++) {
            As[aM[q]][aK[q] + 0] = pA[q].x; As[aM[q]][aK[q] + 1] = pA[q].y;
            As[aM[q]][aK[q] + 2] = pA[q].z; As[aM[q]][aK[q] + 3] = pA[q].w;
            *(float4*)&Bg[bK[q]][bN[q]] = pBg[q];
            *(float4*)&Bu[bK[q]][bN[q]] = pBu[q];
        }
        __syncthreads();

        // prefetch next slab while computing this one
        int kn = k0 + 16;
        if (kn < DD) {
#pragma unroll
            for (int q = 0; q < 2; q++) {
                int tkn = tok[aM[q]];
                pA[q] = (tkn >= 0) ? *(const float4*)(x + (size_t)tkn * DD + kn + aK[q])
                                   : make_float4(0.f, 0.f, 0.f, 0.f);
                pBg[q] = *(const float4*)(wg + (size_t)(kn + bK[q]) * HH + n0 + bN[q]);
                pBu[q] = *(const float4*)(wu + (size_t)(kn + bK[q]) * HH + n0 + bN[q]);
            }
        }

#pragma unroll
        for (int kk = 0; kk < 16; kk++) {
            float a[8];
#pragma unroll
            for (int i = 0; i < 8; i++) a[i] = As[tr * 8 + i][kk];
            float4 bg = *(const float4*)&Bg[kk][tc * 4];
            float4 bu = *(const float4*)&Bu[kk][tc * 4];
#pragma unroll
            for (int i = 0; i < 8; i++) {
                accG[i][0] += a[i] * bg.x; accG[i][1] += a[i] * bg.y;
                accG[i][2] += a[i] * bg.z; accG[i][3] += a[i] * bg.w;
                accU[i][0] += a[i] * bu.x; accU[i][1] += a[i] * bu.y;
                accU[i][2] += a[i] * bu.z; accU[i][3] += a[i] * bu.w;
            }
        }
        __syncthreads();
    }
#pragma unroll
    for (int i = 0; i < 8; i++) {
        int m = m0 + tr * 8 + i;
        if (m < M) {
            float4 o;
            o.x = silu_f(accG[i][0]) * accU[i][0];
            o.y = silu_f(accG[i][1]) * accU[i][1];
            o.z = silu_f(accG[i][2]) * accU[i][2];
            o.w = silu_f(accG[i][3]) * accU[i][3];
            *(float4*)(g_h + ((size_t)(e * TT + m)) * HH + n0 + tc * 4) = o;
        }
    }
}

// ---------------- down GEMM + fused score-weighted combine ----------------
// h[M,704] @ W_down[704,2048], epilogue: y[token] += score * result.
// Each y element receives exactly 2 atomic adds (top-2) onto a zeroed base:
// two-operand fp32 add is commutative bitwise -> deterministic output.
// grid: (DD/64, TT/64, EE), block 128.
__global__ void __launch_bounds__(128) k_down(const float* __restrict__ Wdn,
                                              float* __restrict__ y) {
    int e = blockIdx.z;
    int M = g_cnt[e];
    int m0 = blockIdx.y * 64;
    if (m0 >= M) return;
    int n0 = blockIdx.x * 64;

    __shared__ float As[64][17];
    __shared__ float Bs[16][64];
    __shared__ int   tok[64];
    __shared__ float scr[64];

    int tid = threadIdx.x;
    if (tid < 64) {
        int m = m0 + tid;
        tok[tid] = (m < M) ? g_list[e * TT + m] : -1;
        scr[tid] = (m < M) ? g_sscore[e * TT + m] : 0.f;
    }
    __syncthreads();

    int tr = tid >> 4;
    int tc = tid & 15;
    float acc[8][4];
#pragma unroll
    for (int i = 0; i < 8; i++)
#pragma unroll
        for (int j = 0; j < 4; j++) acc[i][j] = 0.f;

    const float* wd = Wdn + (size_t)e * HH * DD;
    const float* ha = g_h + (size_t)(e * TT) * HH;

    int aM[2], aK[2], bK[2], bN[2];
#pragma unroll
    for (int q = 0; q < 2; q++) {
        int idx = tid * 2 + q;
        aM[q] = idx >> 2;
        aK[q] = (idx & 3) << 2;
        bK[q] = idx >> 4;
        bN[q] = (idx & 15) << 2;
    }

    float4 pA[2], pB[2];
#pragma unroll
    for (int q = 0; q < 2; q++) {
        pA[q] = (m0 + aM[q] < M) ? *(const float4*)(ha + (size_t)(m0 + aM[q]) * HH + aK[q])
                                 : make_float4(0.f, 0.f, 0.f, 0.f);
        pB[q] = *(const float4*)(wd + (size_t)bK[q] * DD + n0 + bN[q]);
    }

    for (int k0 = 0; k0 < HH; k0 += 16) {
#pragma unroll
        for (int q = 0; q < 2; q++) {
            As[aM[q]][aK[q] + 0] = pA[q].x; As[aM[q]][aK[q] + 1] = pA[q].y;
            As[aM[q]][aK[q] + 2] = pA[q].z; As[aM[q]][aK[q] + 3] = pA[q].w;
            *(float4*)&Bs[bK[q]][bN[q]] = pB[q];
        }
        __syncthreads();

        int kn = k0 + 16;
        if (kn < HH) {
#pragma unroll
            for (int q = 0; q < 2; q++) {
                pA[q] = (m0 + aM[q] < M) ? *(const float4*)(ha + (size_t)(m0 + aM[q]) * HH + kn + aK[q])
                                         : make_float4(0.f, 0.f, 0.f, 0.f);
                pB[q] = *(const float4*)(wd + (size_t)(kn + bK[q]) * DD + n0 + bN[q]);
            }
        }

#pragma unroll
        for (int kk = 0; kk < 16; kk++) {
            float a[8];
#pragma unroll
            for (int i = 0; i < 8; i++) a[i] = As[tr * 8 + i][kk];
            float4 b = *(const float4*)&Bs[kk][tc * 4];
#pragma unroll
            for (int i = 0; i < 8; i++) {
                acc[i][0] += a[i] * b.x; acc[i][1] += a[i] * b.y;
                acc[i][2] += a[i] * b.z; acc[i][3] += a[i] * b.w;
            }
        }
        __syncthreads();
    }
#pragma unroll
    for (int i = 0; i < 8; i++) {
        int m = tr * 8 + i;            // row within tile
        if (m0 + m < M) {
            int   tkn = tok[m];
            float sc  = scr[m];
            float* yr = y + (size_t)tkn * DD + n0 + tc * 4;
            atomicAdd(yr + 0, sc * acc[i][0]);
            atomicAdd(yr + 1, sc * acc[i][1]);
            atomicAdd(yr + 2, sc * acc[i][2]);
            atomicAdd(yr + 3, sc * acc[i][3]);
        }
    }
}

// ---------------- balance loss: 0.01*(cv2(importance)+cv2(load)), ddof=1 ----------------
__global__ void k_loss(float* __restrict__ out, int out_size) {
    if (threadIdx.x != 0 || blockIdx.x != 0) return;
    const float eps = 1e-10f;
    float mi = 0.f, ml = 0.f;
#pragma unroll
    for (int e = 0; e < EE; e++) { mi += g_imp[e]; ml += g_load[e]; }
    mi /= EE; ml /= EE;
    float vi = 0.f, vl = 0.f;
#pragma unroll
    for (int e = 0; e < EE; e++) {
        float di = g_imp[e] - mi; vi += di * di;
        float dl = g_load[e] - ml; vl += dl * dl;
    }
    vi /= (EE - 1); vl /= (EE - 1);
    float loss = 0.01f * (vi / (mi * mi + eps) + vl / (ml * ml + eps));
    for (int i = TT * DD; i < out_size; i++) out[i] = loss;
}

extern "C" void kernel_launch(void* const* d_in, const int* in_sizes, int n_in,
                              void* d_out, int out_size) {
    const float* x     = (const float*)d_in[0];
    const float* Wg1   = (const float*)d_in[1];
    const float* Wg2   = (const float*)d_in[2];
    const float* Wgate = (const float*)d_in[3];
    const float* Wup   = (const float*)d_in[4];
    const float* Wdn   = (const float*)d_in[5];
    float* out = (float*)d_out;

    k_init<<<1, 32>>>();
    k_zero<<<(TT * (DD / 4) + 255) / 256, 256>>>(out);
    k_gate<<<TT, 128>>>(x, Wg1, Wg2);
    {
        dim3 g(HH / 64, TT / 64, EE);
        k_up<<<g, 128>>>(x, Wgate, Wup);
    }
    {
        dim3 g(DD / 64, TT / 64, EE);
        k_down<<<g, 128>>>(Wdn, out);
    }
    k_loss<<<1, 1>>>(out, out_size);
}

// round 9
// speedup vs baseline: 1.6209x; 1.6209x over previous
#include <cuda_runtime.h>
#include <cuda_bf16.h>
#include <math.h>

// Problem constants (B=2,S=2048,D=2048,E=8,H=704,K=2)
#define TT 4096
#define DD 2048
#define EE 8
#define HH 704
#define KK 2

// ---------------- scratch ----------------
__device__ int   g_cnt[EE];
__device__ float g_imp[EE];
__device__ float g_load[EE];
__device__ int   g_list[EE * TT];
__device__ float g_sscore[EE * TT];

// bf16 hi/lo splits
__device__ __nv_bfloat16 g_xh[(size_t)TT * DD];
__device__ __nv_bfloat16 g_xl[(size_t)TT * DD];
__device__ __nv_bfloat16 g_wgh[(size_t)EE * HH * DD];  // W_gate^T [e][h][d]
__device__ __nv_bfloat16 g_wgl[(size_t)EE * HH * DD];
__device__ __nv_bfloat16 g_wuh[(size_t)EE * HH * DD];  // W_up^T
__device__ __nv_bfloat16 g_wul[(size_t)EE * HH * DD];
__device__ __nv_bfloat16 g_wdh[(size_t)EE * DD * HH];  // W_down^T [e][d][h]
__device__ __nv_bfloat16 g_wdl[(size_t)EE * DD * HH];
__device__ __nv_bfloat16 g_hh[(size_t)EE * TT * HH];   // SwiGLU hidden hi
__device__ __nv_bfloat16 g_hl[(size_t)EE * TT * HH];   // SwiGLU hidden lo

__device__ __forceinline__ void split2(float v, __nv_bfloat16& h, __nv_bfloat16& l) {
    h = __float2bfloat16(v);
    l = __float2bfloat16(v - __bfloat162float(h));
}
__device__ __forceinline__ unsigned pack2(__nv_bfloat16 a, __nv_bfloat16 b) {
    return (unsigned)__bfloat16_as_ushort(a) | ((unsigned)__bfloat16_as_ushort(b) << 16);
}

#define MMA16816(d, a, b) \
    asm volatile("mma.sync.aligned.m16n8k16.row.col.f32.bf16.bf16.f32 " \
        "{%0,%1,%2,%3}, {%4,%5,%6,%7}, {%8,%9}, {%0,%1,%2,%3};" \
        : "+f"((d)[0]), "+f"((d)[1]), "+f"((d)[2]), "+f"((d)[3]) \
        : "r"((a)[0]), "r"((a)[1]), "r"((a)[2]), "r"((a)[3]), "r"((b)[0]), "r"((b)[1]))

// ---------------- init / zero ----------------
__global__ void k_init() {
    int i = threadIdx.x;
    if (i < EE) { g_cnt[i] = 0; g_imp[i] = 0.f; g_load[i] = 0.f; }
}
__global__ void k_zero(float* __restrict__ y) {
    int i = blockIdx.x * blockDim.x + threadIdx.x;
    if (i < TT * (DD / 4)) ((float4*)y)[i] = make_float4(0.f, 0.f, 0.f, 0.f);
}

// ---------------- split x into bf16 hi/lo ----------------
__global__ void k_split_x(const float* __restrict__ x) {
    int i = blockIdx.x * blockDim.x + threadIdx.x;   // one float4
    if (i >= TT * (DD / 4)) return;
    float4 v = ((const float4*)x)[i];
    __nv_bfloat16 h0, l0, h1, l1, h2, l2, h3, l3;
    split2(v.x, h0, l0); split2(v.y, h1, l1);
    split2(v.z, h2, l2); split2(v.w, h3, l3);
    uint2 ph = make_uint2(pack2(h0, h1), pack2(h2, h3));
    uint2 pl = make_uint2(pack2(l0, l1), pack2(l2, l3));
    ((uint2*)g_xh)[i] = ph;
    ((uint2*)g_xl)[i] = pl;
}

// ---------------- transpose + split weights: in [e][R][C] -> out [e][C][R] ----------------
__global__ void k_split_tr(const float* __restrict__ in,
                           __nv_bfloat16* __restrict__ oh,
                           __nv_bfloat16* __restrict__ ol,
                           int R, int C) {
    __shared__ float t[32][33];
    int e = blockIdx.z;
    const float* ine = in + (size_t)e * R * C;
    __nv_bfloat16* ohe = oh + (size_t)e * R * C;
    __nv_bfloat16* ole = ol + (size_t)e * R * C;
    int r0 = blockIdx.y * 32, c0 = blockIdx.x * 32;
    int tx = threadIdx.x, ty = threadIdx.y;   // 32 x 8
#pragma unroll
    for (int i = 0; i < 32; i += 8)
        t[ty + i][tx] = ine[(size_t)(r0 + ty + i) * C + c0 + tx];
    __syncthreads();
#pragma unroll
    for (int i = 0; i < 32; i += 8) {
        float v = t[tx][ty + i];
        __nv_bfloat16 h, l; split2(v, h, l);
        size_t o = (size_t)(c0 + ty + i) * R + r0 + tx;
        ohe[o] = h; ole[o] = l;
    }
}

// ---------------- gating (unchanged: validated) ----------------
__global__ void k_gate(const float* __restrict__ x,
                       const float* __restrict__ Wg1,
                       const float* __restrict__ Wg2) {
    int t = blockIdx.x;
    int tid = threadIdx.x;
    __shared__ float red[128][9];
    __shared__ float t1[8];

    float p[8] = {0.f,0.f,0.f,0.f,0.f,0.f,0.f,0.f};
    const float* xr = x + (size_t)t * DD;
    for (int d = tid; d < DD; d += 128) {
        float xv = xr[d];
        const float4* w = (const float4*)(Wg1 + (size_t)d * 8);
        float4 w0 = w[0], w1 = w[1];
        p[0] += xv * w0.x; p[1] += xv * w0.y; p[2] += xv * w0.z; p[3] += xv * w0.w;
        p[4] += xv * w1.x; p[5] += xv * w1.y; p[6] += xv * w1.z; p[7] += xv * w1.w;
    }
#pragma unroll
    for (int e = 0; e < 8; e++) red[tid][e] = p[e];
    __syncthreads();
    for (int stride = 64; stride >= 8; stride >>= 1) {
        if (tid < stride) {
#pragma unroll
            for (int e = 0; e < 8; e++) red[tid][e] += red[tid + stride][e];
        }
        __syncthreads();
    }
    if (tid < 8) {
        t1[tid] = tanhf(red[0][tid] + red[1][tid] + red[2][tid] + red[3][tid] +
                        red[4][tid] + red[5][tid] + red[6][tid] + red[7][tid]);
    }
    __syncthreads();
    if (tid == 0) {
        float lg[8];
#pragma unroll
        for (int j = 0; j < 8; j++) {
            float s = 0.f;
#pragma unroll
            for (int e = 0; e < 8; e++) s += t1[e] * Wg2[e * 8 + j];
            lg[j] = s;
        }
        int i0 = 0; float v0 = lg[0];
#pragma unroll
        for (int j = 1; j < 8; j++) if (lg[j] > v0) { v0 = lg[j]; i0 = j; }
        int i1 = -1; float v1 = -1e30f;
#pragma unroll
        for (int j = 0; j < 8; j++) if (j != i0 && lg[j] > v1) { v1 = lg[j]; i1 = j; }
        float e1 = expf(v1 - v0);
        float inv = 1.f / (1.f + e1);
        float s0 = inv, s1 = e1 * inv;

        int p0 = atomicAdd(&g_cnt[i0], 1);
        g_list[i0 * TT + p0] = t;
        g_sscore[i0 * TT + p0] = s0;
        atomicAdd(&g_imp[i0], s0);
        if (s0 > 0.f) atomicAdd(&g_load[i0], 1.f);

        int p1 = atomicAdd(&g_cnt[i1], 1);
        g_list[i1 * TT + p1] = t;
        g_sscore[i1 * TT + p1] = s1;
        atomicAdd(&g_imp[i1], s1);
        if (s1 > 0.f) atomicAdd(&g_load[i1], 1.f);
    }
}

__device__ __forceinline__ float silu_f(float v) { return v / (1.f + expf(-v)); }

// ======== tensor-core fused gate+up GEMM + SwiGLU ========
// C[m,n] = sum_k x[tok[m],k] * W[k,n] via 3xbf16 mma. Tile 64x64, 4 warps (32x32 each).
// grid: (HH/64, TT/64, EE)
#define SP 24   // smem row stride in bf16 (12 words: conflict-free fragment LDS)
__global__ void __launch_bounds__(128) k_up_tc() {
    int e = blockIdx.z;
    int M = g_cnt[e];
    int m0 = blockIdx.y * 64;
    if (m0 >= M) return;
    int n0 = blockIdx.x * 64;

    __shared__ __nv_bfloat16 sAh[64][SP], sAl[64][SP];
    __shared__ __nv_bfloat16 sGh[64][SP], sGl[64][SP];
    __shared__ __nv_bfloat16 sUh[64][SP], sUl[64][SP];
    __shared__ int tok[64];

    int tid = threadIdx.x;
    if (tid < 64) tok[tid] = (m0 + tid < M) ? g_list[e * TT + m0 + tid] : -1;
    __syncthreads();

    int lane = tid & 31, w = tid >> 5;
    int gid = lane >> 2, tid4 = lane & 3;
    int wm = (w & 1) * 32, wn = (w >> 1) * 32;

    float accG[2][4][4], accU[2][4][4];
#pragma unroll
    for (int a = 0; a < 2; a++)
#pragma unroll
        for (int b = 0; b < 4; b++)
#pragma unroll
            for (int c = 0; c < 4; c++) { accG[a][b][c] = 0.f; accU[a][b][c] = 0.f; }

    const __nv_bfloat16* wgh = g_wgh + (size_t)e * HH * DD;
    const __nv_bfloat16* wgl = g_wgl + (size_t)e * HH * DD;
    const __nv_bfloat16* wuh = g_wuh + (size_t)e * HH * DD;
    const __nv_bfloat16* wul = g_wul + (size_t)e * HH * DD;

    int crow = tid >> 1;            // 0..63
    int ckseg = (tid & 1) * 8;      // 0 or 8 (bf16 offset; 8 bf16 = 16B)
    int ctok = tok[crow];
    size_t aoff = (ctok >= 0) ? ((size_t)ctok * DD + ckseg) : 0;
    size_t boff = (size_t)(n0 + crow) * DD + ckseg;

    uint4 pAh, pAl, pGh, pGl, pUh, pUl;
    uint4 zz = make_uint4(0, 0, 0, 0);
    pAh = (ctok >= 0) ? *(const uint4*)(g_xh + aoff) : zz;
    pAl = (ctok >= 0) ? *(const uint4*)(g_xl + aoff) : zz;
    pGh = *(const uint4*)(wgh + boff);
    pGl = *(const uint4*)(wgl + boff);
    pUh = *(const uint4*)(wuh + boff);
    pUl = *(const uint4*)(wul + boff);

    for (int k0 = 0; k0 < DD; k0 += 16) {
        *(uint4*)&sAh[crow][ckseg] = pAh;
        *(uint4*)&sAl[crow][ckseg] = pAl;
        *(uint4*)&sGh[crow][ckseg] = pGh;
        *(uint4*)&sGl[crow][ckseg] = pGl;
        *(uint4*)&sUh[crow][ckseg] = pUh;
        *(uint4*)&sUl[crow][ckseg] = pUl;
        __syncthreads();

        int kn = k0 + 16;
        if (kn < DD) {
            pAh = (ctok >= 0) ? *(const uint4*)(g_xh + aoff + kn) : zz;
            pAl = (ctok >= 0) ? *(const uint4*)(g_xl + aoff + kn) : zz;
            pGh = *(const uint4*)(wgh + boff + kn);
            pGl = *(const uint4*)(wgl + boff + kn);
            pUh = *(const uint4*)(wuh + boff + kn);
            pUl = *(const uint4*)(wul + boff + kn);
        }

        unsigned ah[2][4], al[2][4];
#pragma unroll
        for (int mt = 0; mt < 2; mt++) {
            int r = wm + mt * 16 + gid;
            ah[mt][0] = *(const unsigned*)&sAh[r][tid4 * 2];
            ah[mt][1] = *(const unsigned*)&sAh[r + 8][tid4 * 2];
            ah[mt][2] = *(const unsigned*)&sAh[r][tid4 * 2 + 8];
            ah[mt][3] = *(const unsigned*)&sAh[r + 8][tid4 * 2 + 8];
            al[mt][0] = *(const unsigned*)&sAl[r][tid4 * 2];
            al[mt][1] = *(const unsigned*)&sAl[r + 8][tid4 * 2];
            al[mt][2] = *(const unsigned*)&sAl[r][tid4 * 2 + 8];
            al[mt][3] = *(const unsigned*)&sAl[r + 8][tid4 * 2 + 8];
        }
#pragma unroll
        for (int nt = 0; nt < 4; nt++) {
            int br = wn + nt * 8 + gid;
            unsigned gh[2], gl[2], uh[2], ul[2];
            gh[0] = *(const unsigned*)&sGh[br][tid4 * 2];
            gh[1] = *(const unsigned*)&sGh[br][tid4 * 2 + 8];
            gl[0] = *(const unsigned*)&sGl[br][tid4 * 2];
            gl[1] = *(const unsigned*)&sGl[br][tid4 * 2 + 8];
            uh[0] = *(const unsigned*)&sUh[br][tid4 * 2];
            uh[1] = *(const unsigned*)&sUh[br][tid4 * 2 + 8];
            ul[0] = *(const unsigned*)&sUl[br][tid4 * 2];
            ul[1] = *(const unsigned*)&sUl[br][tid4 * 2 + 8];
#pragma unroll
            for (int mt = 0; mt < 2; mt++) {
                MMA16816(accG[mt][nt], ah[mt], gh);
                MMA16816(accG[mt][nt], ah[mt], gl);
                MMA16816(accG[mt][nt], al[mt], gh);
                MMA16816(accU[mt][nt], ah[mt], uh);
                MMA16816(accU[mt][nt], ah[mt], ul);
                MMA16816(accU[mt][nt], al[mt], uh);
            }
        }
        __syncthreads();
    }

    // epilogue: h = silu(g)*u -> bf16 hi/lo -> g_hh/g_hl [slot][HH]
#pragma unroll
    for (int mt = 0; mt < 2; mt++) {
#pragma unroll
        for (int nt = 0; nt < 4; nt++) {
            int col = n0 + wn + nt * 8 + tid4 * 2;
            int mA = wm + mt * 16 + gid;       // local rows
            int mB = mA + 8;
#pragma unroll
            for (int half = 0; half < 2; half++) {
                int ml = half ? mB : mA;
                if (m0 + ml < M) {
                    float gg0 = accG[mt][nt][half * 2 + 0];
                    float gg1 = accG[mt][nt][half * 2 + 1];
                    float uu0 = accU[mt][nt][half * 2 + 0];
                    float uu1 = accU[mt][nt][half * 2 + 1];
                    float h0 = silu_f(gg0) * uu0;
                    float h1 = silu_f(gg1) * uu1;
                    __nv_bfloat16 h0h, h0l, h1h, h1l;
                    split2(h0, h0h, h0l); split2(h1, h1h, h1l);
                    size_t o = ((size_t)(e * TT + m0 + ml)) * HH + col;
                    *(unsigned*)(g_hh + o) = pack2(h0h, h1h);
                    *(unsigned*)(g_hl + o) = pack2(h0l, h1l);
                }
            }
        }
    }
}

// ======== tensor-core down GEMM + fused score-weighted combine ========
// y[tok[m]] += score[m] * (h[m] @ W_down).  grid: (DD/64, TT/64, EE)
__global__ void __launch_bounds__(128) k_down_tc(float* __restrict__ y) {
    int e = blockIdx.z;
    int M = g_cnt[e];
    int m0 = blockIdx.y * 64;
    if (m0 >= M) return;
    int n0 = blockIdx.x * 64;

    __shared__ __nv_bfloat16 sAh[64][SP], sAl[64][SP];
    __shared__ __nv_bfloat16 sBh[64][SP], sBl[64][SP];
    __shared__ int   tok[64];
    __shared__ float scr[64];

    int tid = threadIdx.x;
    if (tid < 64) {
        int m = m0 + tid;
        tok[tid] = (m < M) ? g_list[e * TT + m] : -1;
        scr[tid] = (m < M) ? g_sscore[e * TT + m] : 0.f;
    }
    __syncthreads();

    int lane = tid & 31, w = tid >> 5;
    int gid = lane >> 2, tid4 = lane & 3;
    int wm = (w & 1) * 32, wn = (w >> 1) * 32;

    float acc[2][4][4];
#pragma unroll
    for (int a = 0; a < 2; a++)
#pragma unroll
        for (int b = 0; b < 4; b++)
#pragma unroll
            for (int c = 0; c < 4; c++) acc[a][b][c] = 0.f;

    const __nv_bfloat16* wdh = g_wdh + (size_t)e * DD * HH;
    const __nv_bfloat16* wdl = g_wdl + (size_t)e * DD * HH;
    const __nv_bfloat16* hh = g_hh + (size_t)(e * TT) * HH;
    const __nv_bfloat16* hl = g_hl + (size_t)(e * TT) * HH;

    int crow = tid >> 1;
    int ckseg = (tid & 1) * 8;
    int avalid = (m0 + crow < M);
    size_t aoff = (size_t)(m0 + crow) * HH + ckseg;
    size_t boff = (size_t)(n0 + crow) * HH + ckseg;

    uint4 pAh, pAl, pBh, pBl;
    uint4 zz = make_uint4(0, 0, 0, 0);
    pAh = avalid ? *(const uint4*)(hh + aoff) : zz;
    pAl = avalid ? *(const uint4*)(hl + aoff) : zz;
    pBh = *(const uint4*)(wdh + boff);
    pBl = *(const uint4*)(wdl + boff);

    for (int k0 = 0; k0 < HH; k0 += 16) {
        *(uint4*)&sAh[crow][ckseg] = pAh;
        *(uint4*)&sAl[crow][ckseg] = pAl;
        *(uint4*)&sBh[crow][ckseg] = pBh;
        *(uint4*)&sBl[crow][ckseg] = pBl;
        __syncthreads();

        int kn = k0 + 16;
        if (kn < HH) {
            pAh = avalid ? *(const uint4*)(hh + aoff + kn) : zz;
            pAl = avalid ? *(const uint4*)(hl + aoff + kn) : zz;
            pBh = *(const uint4*)(wdh + boff + kn);
            pBl = *(const uint4*)(wdl + boff + kn);
        }

        unsigned ah[2][4], al[2][4];
#pragma unroll
        for (int mt = 0; mt < 2; mt++) {
            int r = wm + mt * 16 + gid;
            ah[mt][0] = *(const unsigned*)&sAh[r][tid4 * 2];
            ah[mt][1] = *(const unsigned*)&sAh[r + 8][tid4 * 2];
            ah[mt][2] = *(const unsigned*)&sAh[r][tid4 * 2 + 8];
            ah[mt][3] = *(const unsigned*)&sAh[r + 8][tid4 * 2 + 8];
            al[mt][0] = *(const unsigned*)&sAl[r][tid4 * 2];
            al[mt][1] = *(const unsigned*)&sAl[r + 8][tid4 * 2];
            al[mt][2] = *(const unsigned*)&sAl[r][tid4 * 2 + 8];
            al[mt][3] = *(const unsigned*)&sAl[r + 8][tid4 * 2 + 8];
        }
#pragma unroll
        for (int nt = 0; nt < 4; nt++) {
            int br = wn + nt * 8 + gid;
            unsigned bh[2], bl[2];
            bh[0] = *(const unsigned*)&sBh[br][tid4 * 2];
            bh[1] = *(const unsigned*)&sBh[br][tid4 * 2 + 8];
            bl[0] = *(const unsigned*)&sBl[br][tid4 * 2];
            bl[1] = *(const unsigned*)&sBl[br][tid4 * 2 + 8];
#pragma unroll
            for (int mt = 0; mt < 2; mt++) {
                MMA16816(acc[mt][nt], ah[mt], bh);
                MMA16816(acc[mt][nt], ah[mt], bl);
                MMA16816(acc[mt][nt], al[mt], bh);
            }
        }
        __syncthreads();
    }

    // epilogue: atomic score-weighted combine into y (exactly 2 adds per element -> deterministic)
#pragma unroll
    for (int mt = 0; mt < 2; mt++) {
#pragma unroll
        for (int nt = 0; nt < 4; nt++) {
            int col = n0 + wn + nt * 8 + tid4 * 2;
#pragma unroll
            for (int half = 0; half < 2; half++) {
                int ml = wm + mt * 16 + gid + half * 8;
                if (m0 + ml < M) {
                    int   tkn = tok[ml];
                    float sc  = scr[ml];
                    float* yr = y + (size_t)tkn * DD + col;
                    atomicAdd(yr + 0, sc * acc[mt][nt][half * 2 + 0]);
                    atomicAdd(yr + 1, sc * acc[mt][nt][half * 2 + 1]);
                }
            }
        }
    }
}

// ---------------- balance loss ----------------
__global__ void k_loss(float* __restrict__ out, int out_size) {
    if (threadIdx.x != 0 || blockIdx.x != 0) return;
    const float eps = 1e-10f;
    float mi = 0.f, ml = 0.f;
#pragma unroll
    for (int e = 0; e < EE; e++) { mi += g_imp[e]; ml += g_load[e]; }
    mi /= EE; ml /= EE;
    float vi = 0.f, vl = 0.f;
#pragma unroll
    for (int e = 0; e < EE; e++) {
        float di = g_imp[e] - mi; vi += di * di;
        float dl = g_load[e] - ml; vl += dl * dl;
    }
    vi /= (EE - 1); vl /= (EE - 1);
    float loss = 0.01f * (vi / (mi * mi + eps) + vl / (ml * ml + eps));
    for (int i = TT * DD; i < out_size; i++) out[i] = loss;
}

extern "C" void kernel_launch(void* const* d_in, const int* in_sizes, int n_in,
                              void* d_out, int out_size) {
    const float* x     = (const float*)d_in[0];
    const float* Wg1   = (const float*)d_in[1];
    const float* Wg2   = (const float*)d_in[2];
    const float* Wgate = (const float*)d_in[3];
    const float* Wup   = (const float*)d_in[4];
    const float* Wdn   = (const float*)d_in[5];
    float* out = (float*)d_out;

    k_init<<<1, 32>>>();
    k_zero<<<(TT * (DD / 4) + 255) / 256, 256>>>(out);
    k_gate<<<TT, 128>>>(x, Wg1, Wg2);
    k_split_x<<<(TT * (DD / 4) + 255) / 256, 256>>>(x);

    // device-symbol addresses are host-visible via cudaGetSymbolAddress; use kernels w/ symbols directly
    {
        dim3 tb(32, 8);
        dim3 tg(HH / 32, DD / 32, EE);     // W_gate/W_up: [D][H] -> [H][D]
        void *oh, *ol;
        cudaGetSymbolAddress(&oh, g_wgh); cudaGetSymbolAddress(&ol, g_wgl);
        k_split_tr<<<tg, tb>>>(Wgate, (__nv_bfloat16*)oh, (__nv_bfloat16*)ol, DD, HH);
        cudaGetSymbolAddress(&oh, g_wuh); cudaGetSymbolAddress(&ol, g_wul);
        k_split_tr<<<tg, tb>>>(Wup, (__nv_bfloat16*)oh, (__nv_bfloat16*)ol, DD, HH);
        dim3 tg2(DD / 32, HH / 32, EE);    // W_down: [H][D] -> [D][H]
        cudaGetSymbolAddress(&oh, g_wdh); cudaGetSymbolAddress(&ol, g_wdl);
        k_split_tr<<<tg2, tb>>>(Wdn, (__nv_bfloat16*)oh, (__nv_bfloat16*)ol, HH, DD);
    }

    {
        dim3 g(HH / 64, TT / 64, EE);
        k_up_tc<<<g, 128>>>();
    }
    {
        dim3 g(DD / 64, TT / 64, EE);
        k_down_tc<<<g, 128>>>(out);
    }
    k_loss<<<1, 1>>>(out, out_size);
}

// round 14
// speedup vs baseline: 1.7060x; 1.0525x over previous
#include <cuda_runtime.h>
#include <cuda_bf16.h>
#include <math.h>

// Problem constants (B=2,S=2048,D=2048,E=8,H=704,K=2)
#define TT 4096
#define DD 2048
#define EE 8
#define HH 704
#define KK 2

// ---------------- scratch ----------------
__device__ int   g_cnt[EE];
__device__ float g_imp[EE];
__device__ float g_load[EE];
__device__ int   g_list[EE * TT];
__device__ float g_sscore[EE * TT];

// bf16 hi/lo splits
__device__ __nv_bfloat16 g_xh[(size_t)TT * DD];
__device__ __nv_bfloat16 g_xl[(size_t)TT * DD];
__device__ __nv_bfloat16 g_wgh[(size_t)EE * HH * DD];  // W_gate^T [e][h][d]
__device__ __nv_bfloat16 g_wgl[(size_t)EE * HH * DD];
__device__ __nv_bfloat16 g_wuh[(size_t)EE * HH * DD];  // W_up^T
__device__ __nv_bfloat16 g_wul[(size_t)EE * HH * DD];
__device__ __nv_bfloat16 g_wdh[(size_t)EE * DD * HH];  // W_down^T [e][d][h]
__device__ __nv_bfloat16 g_wdl[(size_t)EE * DD * HH];
__device__ __nv_bfloat16 g_hh[(size_t)EE * TT * HH];   // SwiGLU hidden hi
__device__ __nv_bfloat16 g_hl[(size_t)EE * TT * HH];   // SwiGLU hidden lo

__device__ __forceinline__ void split2(float v, __nv_bfloat16& h, __nv_bfloat16& l) {
    h = __float2bfloat16(v);
    l = __float2bfloat16(v - __bfloat162float(h));
}
__device__ __forceinline__ unsigned pack2(__nv_bfloat16 a, __nv_bfloat16 b) {
    return (unsigned)__bfloat16_as_ushort(a) | ((unsigned)__bfloat16_as_ushort(b) << 16);
}
__device__ __forceinline__ unsigned smem_u32(const void* p) {
    return (unsigned)__cvta_generic_to_shared(p);
}

#define MMA16816(d, a, b) \
    asm volatile("mma.sync.aligned.m16n8k16.row.col.f32.bf16.bf16.f32 " \
        "{%0,%1,%2,%3}, {%4,%5,%6,%7}, {%8,%9}, {%0,%1,%2,%3};" \
        : "+f"((d)[0]), "+f"((d)[1]), "+f"((d)[2]), "+f"((d)[3]) \
        : "r"((a)[0]), "r"((a)[1]), "r"((a)[2]), "r"((a)[3]), "r"((b)[0]), "r"((b)[1]))

#define LDSM_X4(d0, d1, d2, d3, addr) \
    asm volatile("ldmatrix.sync.aligned.m8n8.x4.shared.b16 {%0,%1,%2,%3}, [%4];" \
        : "=r"(d0), "=r"(d1), "=r"(d2), "=r"(d3) : "r"(addr))

// ---------------- init / zero ----------------
__global__ void k_init() {
    int i = threadIdx.x;
    if (i < EE) { g_cnt[i] = 0; g_imp[i] = 0.f; g_load[i] = 0.f; }
}
__global__ void k_zero(float* __restrict__ y) {
    int i = blockIdx.x * blockDim.x + threadIdx.x;
    if (i < TT * (DD / 4)) ((float4*)y)[i] = make_float4(0.f, 0.f, 0.f, 0.f);
}

// ---------------- split x into bf16 hi/lo ----------------
__global__ void k_split_x(const float* __restrict__ x) {
    int i = blockIdx.x * blockDim.x + threadIdx.x;   // one float4
    if (i >= TT * (DD / 4)) return;
    float4 v = ((const float4*)x)[i];
    __nv_bfloat16 h0, l0, h1, l1, h2, l2, h3, l3;
    split2(v.x, h0, l0); split2(v.y, h1, l1);
    split2(v.z, h2, l2); split2(v.w, h3, l3);
    uint2 ph = make_uint2(pack2(h0, h1), pack2(h2, h3));
    uint2 pl = make_uint2(pack2(l0, l1), pack2(l2, l3));
    ((uint2*)g_xh)[i] = ph;
    ((uint2*)g_xl)[i] = pl;
}

// ---------------- transpose + split weights: in [e][R][C] -> out [e][C][R] ----------------
__global__ void k_split_tr(const float* __restrict__ in,
                           __nv_bfloat16* __restrict__ oh,
                           __nv_bfloat16* __restrict__ ol,
                           int R, int C) {
    __shared__ float t[32][33];
    int e = blockIdx.z;
    const float* ine = in + (size_t)e * R * C;
    __nv_bfloat16* ohe = oh + (size_t)e * R * C;
    __nv_bfloat16* ole = ol + (size_t)e * R * C;
    int r0 = blockIdx.y * 32, c0 = blockIdx.x * 32;
    int tx = threadIdx.x, ty = threadIdx.y;   // 32 x 8
#pragma unroll
    for (int i = 0; i < 32; i += 8)
        t[ty + i][tx] = ine[(size_t)(r0 + ty + i) * C + c0 + tx];
    __syncthreads();
#pragma unroll
    for (int i = 0; i < 32; i += 8) {
        float v = t[tx][ty + i];
        __nv_bfloat16 h, l; split2(v, h, l);
        size_t o = (size_t)(c0 + ty + i) * R + r0 + tx;
        ohe[o] = h; ole[o] = l;
    }
}

// ---------------- gating (unchanged: validated) ----------------
__global__ void k_gate(const float* __restrict__ x,
                       const float* __restrict__ Wg1,
                       const float* __restrict__ Wg2) {
    int t = blockIdx.x;
    int tid = threadIdx.x;
    __shared__ float red[128][9];
    __shared__ float t1[8];

    float p[8] = {0.f,0.f,0.f,0.f,0.f,0.f,0.f,0.f};
    const float* xr = x + (size_t)t * DD;
    for (int d = tid; d < DD; d += 128) {
        float xv = xr[d];
        const float4* w = (const float4*)(Wg1 + (size_t)d * 8);
        float4 w0 = w[0], w1 = w[1];
        p[0] += xv * w0.x; p[1] += xv * w0.y; p[2] += xv * w0.z; p[3] += xv * w0.w;
        p[4] += xv * w1.x; p[5] += xv * w1.y; p[6] += xv * w1.z; p[7] += xv * w1.w;
    }
#pragma unroll
    for (int e = 0; e < 8; e++) red[tid][e] = p[e];
    __syncthreads();
    for (int stride = 64; stride >= 8; stride >>= 1) {
        if (tid < stride) {
#pragma unroll
            for (int e = 0; e < 8; e++) red[tid][e] += red[tid + stride][e];
        }
        __syncthreads();
    }
    if (tid < 8) {
        t1[tid] = tanhf(red[0][tid] + red[1][tid] + red[2][tid] + red[3][tid] +
                        red[4][tid] + red[5][tid] + red[6][tid] + red[7][tid]);
    }
    __syncthreads();
    if (tid == 0) {
        float lg[8];
#pragma unroll
        for (int j = 0; j < 8; j++) {
            float s = 0.f;
#pragma unroll
            for (int e = 0; e < 8; e++) s += t1[e] * Wg2[e * 8 + j];
            lg[j] = s;
        }
        int i0 = 0; float v0 = lg[0];
#pragma unroll
        for (int j = 1; j < 8; j++) if (lg[j] > v0) { v0 = lg[j]; i0 = j; }
        int i1 = -1; float v1 = -1e30f;
#pragma unroll
        for (int j = 0; j < 8; j++) if (j != i0 && lg[j] > v1) { v1 = lg[j]; i1 = j; }
        float e1 = expf(v1 - v0);
        float inv = 1.f / (1.f + e1);
        float s0 = inv, s1 = e1 * inv;

        int p0 = atomicAdd(&g_cnt[i0], 1);
        g_list[i0 * TT + p0] = t;
        g_sscore[i0 * TT + p0] = s0;
        atomicAdd(&g_imp[i0], s0);
        if (s0 > 0.f) atomicAdd(&g_load[i0], 1.f);

        int p1 = atomicAdd(&g_cnt[i1], 1);
        g_list[i1 * TT + p1] = t;
        g_sscore[i1 * TT + p1] = s1;
        atomicAdd(&g_imp[i1], s1);
        if (s1 > 0.f) atomicAdd(&g_load[i1], 1.f);
    }
}

__device__ __forceinline__ float silu_f(float v) { return v / (1.f + expf(-v)); }

// ======== tensor-core fused gate+up GEMM + SwiGLU (ldmatrix fragments) ========
// grid: (HH/64, TT/64, EE), 128 threads (4 warps, 32x32 C-tile each).
#define SP 24   // smem row stride in bf16; 12-word stride -> conflict-free LDSM
__global__ void __launch_bounds__(128) k_up_tc() {
    int e = blockIdx.z;
    int M = g_cnt[e];
    int m0 = blockIdx.y * 64;
    if (m0 >= M) return;
    int n0 = blockIdx.x * 64;

    __shared__ __nv_bfloat16 sAh[64][SP], sAl[64][SP];
    __shared__ __nv_bfloat16 sGh[64][SP], sGl[64][SP];
    __shared__ __nv_bfloat16 sUh[64][SP], sUl[64][SP];
    __shared__ int tok[64];

    int tid = threadIdx.x;
    if (tid < 64) tok[tid] = (m0 + tid < M) ? g_list[e * TT + m0 + tid] : -1;
    __syncthreads();

    int lane = tid & 31, w = tid >> 5;
    int gid = lane >> 2, tid4 = lane & 3;
    int wm = (w & 1) * 32, wn = (w >> 1) * 32;

    // ldmatrix per-lane addresses (loop-invariant)
    int q = lane >> 3, lr = lane & 7;
    int arow = lr + (q & 1) * 8, acol = (q & 2) ? 8 : 0;   // A: q0=a0,q1=a1,q2=a2,q3=a3
    int brow = lr + (q >> 1) * 8, bcol = (q & 1) ? 8 : 0;  // B: q0=b0(nt),q1=b1(nt),q2=b0(nt+1),q3=b1(nt+1)
    unsigned adAh[2], adAl[2];
#pragma unroll
    for (int mt = 0; mt < 2; mt++) {
        adAh[mt] = smem_u32(&sAh[wm + mt * 16 + arow][acol]);
        adAl[mt] = smem_u32(&sAl[wm + mt * 16 + arow][acol]);
    }
    unsigned adGh[2], adGl[2], adUh[2], adUl[2];
#pragma unroll
    for (int np = 0; np < 2; np++) {
        int r = wn + np * 16 + brow;
        adGh[np] = smem_u32(&sGh[r][bcol]);
        adGl[np] = smem_u32(&sGl[r][bcol]);
        adUh[np] = smem_u32(&sUh[r][bcol]);
        adUl[np] = smem_u32(&sUl[r][bcol]);
    }

    float accG[2][4][4], accU[2][4][4];
#pragma unroll
    for (int a = 0; a < 2; a++)
#pragma unroll
        for (int b = 0; b < 4; b++)
#pragma unroll
            for (int c = 0; c < 4; c++) { accG[a][b][c] = 0.f; accU[a][b][c] = 0.f; }

    const __nv_bfloat16* wgh = g_wgh + (size_t)e * HH * DD;
    const __nv_bfloat16* wgl = g_wgl + (size_t)e * HH * DD;
    const __nv_bfloat16* wuh = g_wuh + (size_t)e * HH * DD;
    const __nv_bfloat16* wul = g_wul + (size_t)e * HH * DD;

    int crow = tid >> 1;            // 0..63
    int ckseg = (tid & 1) * 8;      // 0 or 8 bf16 (16B)
    int ctok = tok[crow];
    size_t aoff = (ctok >= 0) ? ((size_t)ctok * DD + ckseg) : 0;
    size_t boff = (size_t)(n0 + crow) * DD + ckseg;

    uint4 pAh, pAl, pGh, pGl, pUh, pUl;
    uint4 zz = make_uint4(0, 0, 0, 0);
    pAh = (ctok >= 0) ? *(const uint4*)(g_xh + aoff) : zz;
    pAl = (ctok >= 0) ? *(const uint4*)(g_xl + aoff) : zz;
    pGh = *(const uint4*)(wgh + boff);
    pGl = *(const uint4*)(wgl + boff);
    pUh = *(const uint4*)(wuh + boff);
    pUl = *(const uint4*)(wul + boff);

    for (int k0 = 0; k0 < DD; k0 += 16) {
        *(uint4*)&sAh[crow][ckseg] = pAh;
        *(uint4*)&sAl[crow][ckseg] = pAl;
        *(uint4*)&sGh[crow][ckseg] = pGh;
        *(uint4*)&sGl[crow][ckseg] = pGl;
        *(uint4*)&sUh[crow][ckseg] = pUh;
        *(uint4*)&sUl[crow][ckseg] = pUl;
        __syncthreads();

        int kn = k0 + 16;
        if (kn < DD) {
            pAh = (ctok >= 0) ? *(const uint4*)(g_xh + aoff + kn) : zz;
            pAl = (ctok >= 0) ? *(const uint4*)(g_xl + aoff + kn) : zz;
            pGh = *(const uint4*)(wgh + boff + kn);
            pGl = *(const uint4*)(wgl + boff + kn);
            pUh = *(const uint4*)(wuh + boff + kn);
            pUl = *(const uint4*)(wul + boff + kn);
        }

        unsigned ah[2][4], al[2][4];
#pragma unroll
        for (int mt = 0; mt < 2; mt++) {
            LDSM_X4(ah[mt][0], ah[mt][1], ah[mt][2], ah[mt][3], adAh[mt]);
            LDSM_X4(al[mt][0], al[mt][1], al[mt][2], al[mt][3], adAl[mt]);
        }
#pragma unroll
        for (int np = 0; np < 2; np++) {
            unsigned gh[4], gl[4], uh[4], ul[4];
            LDSM_X4(gh[0], gh[1], gh[2], gh[3], adGh[np]);
            LDSM_X4(gl[0], gl[1], gl[2], gl[3], adGl[np]);
            LDSM_X4(uh[0], uh[1], uh[2], uh[3], adUh[np]);
            LDSM_X4(ul[0], ul[1], ul[2], ul[3], adUl[np]);
#pragma unroll
            for (int s = 0; s < 2; s++) {          // two n-tiles per ldsm pair
                int nt = np * 2 + s;
#pragma unroll
                for (int mt = 0; mt < 2; mt++) {
                    MMA16816(accG[mt][nt], ah[mt], gh + s * 2);
                    MMA16816(accG[mt][nt], ah[mt], gl + s * 2);
                    MMA16816(accG[mt][nt], al[mt], gh + s * 2);
                    MMA16816(accU[mt][nt], ah[mt], uh + s * 2);
                    MMA16816(accU[mt][nt], ah[mt], ul + s * 2);
                    MMA16816(accU[mt][nt], al[mt], uh + s * 2);
                }
            }
        }
        __syncthreads();
    }

    // epilogue: h = silu(g)*u -> bf16 hi/lo
#pragma unroll
    for (int mt = 0; mt < 2; mt++) {
#pragma unroll
        for (int nt = 0; nt < 4; nt++) {
            int col = n0 + wn + nt * 8 + tid4 * 2;
            int mA = wm + mt * 16 + gid;
#pragma unroll
            for (int half = 0; half < 2; half++) {
                int ml = mA + half * 8;
                if (m0 + ml < M) {
                    float h0 = silu_f(accG[mt][nt][half * 2 + 0]) * accU[mt][nt][half * 2 + 0];
                    float h1 = silu_f(accG[mt][nt][half * 2 + 1]) * accU[mt][nt][half * 2 + 1];
                    __nv_bfloat16 h0h, h0l, h1h, h1l;
                    split2(h0, h0h, h0l); split2(h1, h1h, h1l);
                    size_t o = ((size_t)(e * TT + m0 + ml)) * HH + col;
                    *(unsigned*)(g_hh + o) = pack2(h0h, h1h);
                    *(unsigned*)(g_hl + o) = pack2(h0l, h1l);
                }
            }
        }
    }
}

// ======== tensor-core down GEMM + fused score-weighted combine (ldmatrix) ========
// grid: (DD/64, TT/64, EE)
__global__ void __launch_bounds__(128) k_down_tc(float* __restrict__ y) {
    int e = blockIdx.z;
    int M = g_cnt[e];
    int m0 = blockIdx.y * 64;
    if (m0 >= M) return;
    int n0 = blockIdx.x * 64;

    __shared__ __nv_bfloat16 sAh[64][SP], sAl[64][SP];
    __shared__ __nv_bfloat16 sBh[64][SP], sBl[64][SP];
    __shared__ int   tok[64];
    __shared__ float scr[64];

    int tid = threadIdx.x;
    if (tid < 64) {
        int m = m0 + tid;
        tok[tid] = (m < M) ? g_list[e * TT + m] : -1;
        scr[tid] = (m < M) ? g_sscore[e * TT + m] : 0.f;
    }
    __syncthreads();

    int lane = tid & 31, w = tid >> 5;
    int gid = lane >> 2, tid4 = lane & 3;
    int wm = (w & 1) * 32, wn = (w >> 1) * 32;

    int q = lane >> 3, lr = lane & 7;
    int arow = lr + (q & 1) * 8, acol = (q & 2) ? 8 : 0;
    int brow = lr + (q >> 1) * 8, bcol = (q & 1) ? 8 : 0;
    unsigned adAh[2], adAl[2], adBh[2], adBl[2];
#pragma unroll
    for (int mt = 0; mt < 2; mt++) {
        adAh[mt] = smem_u32(&sAh[wm + mt * 16 + arow][acol]);
        adAl[mt] = smem_u32(&sAl[wm + mt * 16 + arow][acol]);
    }
#pragma unroll
    for (int np = 0; np < 2; np++) {
        int r = wn + np * 16 + brow;
        adBh[np] = smem_u32(&sBh[r][bcol]);
        adBl[np] = smem_u32(&sBl[r][bcol]);
    }

    float acc[2][4][4];
#pragma unroll
    for (int a = 0; a < 2; a++)
#pragma unroll
        for (int b = 0; b < 4; b++)
#pragma unroll
            for (int c = 0; c < 4; c++) acc[a][b][c] = 0.f;

    const __nv_bfloat16* wdh = g_wdh + (size_t)e * DD * HH;
    const __nv_bfloat16* wdl = g_wdl + (size_t)e * DD * HH;
    const __nv_bfloat16* hh = g_hh + (size_t)(e * TT) * HH;
    const __nv_bfloat16* hl = g_hl + (size_t)(e * TT) * HH;

    int crow = tid >> 1;
    int ckseg = (tid & 1) * 8;
    int avalid = (m0 + crow < M);
    size_t aoff = (size_t)(m0 + crow) * HH + ckseg;
    size_t boff = (size_t)(n0 + crow) * HH + ckseg;

    uint4 pAh, pAl, pBh, pBl;
    uint4 zz = make_uint4(0, 0, 0, 0);
    pAh = avalid ? *(const uint4*)(hh + aoff) : zz;
    pAl = avalid ? *(const uint4*)(hl + aoff) : zz;
    pBh = *(const uint4*)(wdh + boff);
    pBl = *(const uint4*)(wdl + boff);

    for (int k0 = 0; k0 < HH; k0 += 16) {
        *(uint4*)&sAh[crow][ckseg] = pAh;
        *(uint4*)&sAl[crow][ckseg] = pAl;
        *(uint4*)&sBh[crow][ckseg] = pBh;
        *(uint4*)&sBl[crow][ckseg] = pBl;
        __syncthreads();

        int kn = k0 + 16;
        if (kn < HH) {
            pAh = avalid ? *(const uint4*)(hh + aoff + kn) : zz;
            pAl = avalid ? *(const uint4*)(hl + aoff + kn) : zz;
            pBh = *(const uint4*)(wdh + boff + kn);
            pBl = *(const uint4*)(wdl + boff + kn);
        }

        unsigned ah[2][4], al[2][4];
#pragma unroll
        for (int mt = 0; mt < 2; mt++) {
            LDSM_X4(ah[mt][0], ah[mt][1], ah[mt][2], ah[mt][3], adAh[mt]);
            LDSM_X4(al[mt][0], al[mt][1], al[mt][2], al[mt][3], adAl[mt]);
        }
#pragma unroll
        for (int np = 0; np < 2; np++) {
            unsigned bh[4], bl[4];
            LDSM_X4(bh[0], bh[1], bh[2], bh[3], adBh[np]);
            LDSM_X4(bl[0], bl[1], bl[2], bl[3], adBl[np]);
#pragma unroll
            for (int s = 0; s < 2; s++) {
                int nt = np * 2 + s;
#pragma unroll
                for (int mt = 0; mt < 2; mt++) {
                    MMA16816(acc[mt][nt], ah[mt], bh + s * 2);
                    MMA16816(acc[mt][nt], ah[mt], bl + s * 2);
                    MMA16816(acc[mt][nt], al[mt], bh + s * 2);
                }
            }
        }
        __syncthreads();
    }

    // epilogue: atomic score-weighted combine (exactly 2 adds per y element -> deterministic)
#pragma unroll
    for (int mt = 0; mt < 2; mt++) {
#pragma unroll
        for (int nt = 0; nt < 4; nt++) {
            int col = n0 + wn + nt * 8 + tid4 * 2;
#pragma unroll
            for (int half = 0; half < 2; half++) {
                int ml = wm + mt * 16 + gid + half * 8;
                if (m0 + ml < M) {
                    int   tkn = tok[ml];
                    float sc  = scr[ml];
                    float* yr = y + (size_t)tkn * DD + col;
                    atomicAdd(yr + 0, sc * acc[mt][nt][half * 2 + 0]);
                    atomicAdd(yr + 1, sc * acc[mt][nt][half * 2 + 1]);
                }
            }
        }
    }
}

// ---------------- balance loss ----------------
__global__ void k_loss(float* __restrict__ out, int out_size) {
    if (threadIdx.x != 0 || blockIdx.x != 0) return;
    const float eps = 1e-10f;
    float mi = 0.f, ml = 0.f;
#pragma unroll
    for (int e = 0; e < EE; e++) { mi += g_imp[e]; ml += g_load[e]; }
    mi /= EE; ml /= EE;
    float vi = 0.f, vl = 0.f;
#pragma unroll
    for (int e = 0; e < EE; e++) {
        float di = g_imp[e] - mi; vi += di * di;
        float dl = g_load[e] - ml; vl += dl * dl;
    }
    vi /= (EE - 1); vl /= (EE - 1);
    float loss = 0.01f * (vi / (mi * mi + eps) + vl / (ml * ml + eps));
    for (int i = TT * DD; i < out_size; i++) out[i] = loss;
}

extern "C" void kernel_launch(void* const* d_in, const int* in_sizes, int n_in,
                              void* d_out, int out_size) {
    const float* x     = (const float*)d_in[0];
    const float* Wg1   = (const float*)d_in[1];
    const float* Wg2   = (const float*)d_in[2];
    const float* Wgate = (const float*)d_in[3];
    const float* Wup   = (const float*)d_in[4];
    const float* Wdn   = (const float*)d_in[5];
    float* out = (float*)d_out;

    k_init<<<1, 32>>>();
    k_zero<<<(TT * (DD / 4) + 255) / 256, 256>>>(out);
    k_gate<<<TT, 128>>>(x, Wg1, Wg2);
    k_split_x<<<(TT * (DD / 4) + 255) / 256, 256>>>(x);

    {
        dim3 tb(32, 8);
        dim3 tg(HH / 32, DD / 32, EE);     // W_gate/W_up: [D][H] -> [H][D]
        void *oh, *ol;
        cudaGetSymbolAddress(&oh, g_wgh); cudaGetSymbolAddress(&ol, g_wgl);
        k_split_tr<<<tg, tb>>>(Wgate, (__nv_bfloat16*)oh, (__nv_bfloat16*)ol, DD, HH);
        cudaGetSymbolAddress(&oh, g_wuh); cudaGetSymbolAddress(&ol, g_wul);
        k_split_tr<<<tg, tb>>>(Wup, (__nv_bfloat16*)oh, (__nv_bfloat16*)ol, DD, HH);
        dim3 tg2(DD / 32, HH / 32, EE);    // W_down: [H][D] -> [D][H]
        cudaGetSymbolAddress(&oh, g_wdh); cudaGetSymbolAddress(&ol, g_wdl);
        k_split_tr<<<tg2, tb>>>(Wdn, (__nv_bfloat16*)oh, (__nv_bfloat16*)ol, HH, DD);
    }

    {
        dim3 g(HH / 64, TT / 64, EE);
        k_up_tc<<<g, 128>>>();
    }
    {
        dim3 g(DD / 64, TT / 64, EE);
        k_down_tc<<<g, 128>>>(out);
    }
    k_loss<<<1, 1>>>(out, out_size);
}